// round 16
// baseline (speedup 1.0000x reference)
#include <cuda_runtime.h>
#include <cuda_bf16.h>
#include <math.h>
#include <mma.h>

using namespace nvcuda;

// ---------------------------------------------------------------------------
// FrozenLSLModel == (pred, out_pos) lookup table (u <= 64 distinct preds).
// R16 = R15 with gemm1 moved to tensor cores: TF32x4 decomposition
// (hi/lo split of both operands, all 4 products, fp32 accumulate) gives
// fp32-level precision on the logits while offloading the 377M-MAC GEMM
// from the saturated FFMA pipe to the idle tensor pipe.
// ---------------------------------------------------------------------------

#define HID 768
#define BITS 64
#define T_ROWS (BITS * BITS)

#define KSD 6                    // decoder l1 K-slices
#define KSLICED (HID / KSD)      // 128
#define KS1 6                    // gemm1 K-slices
#define KSLICE1 (HID / KS1)      // 128
#define KS2 8                    // gemm2 K-slices
#define KSLICE2 (HID / KS2)      // 96

__device__ float g_d1[KSD][BITS][HID];        // decoder l1 partials
__device__ float g_p1[KS1][T_ROWS][HID];      // gemm1 partials
__device__ float g_part[KS2][T_ROWS][BITS];   // gemm2 partials
__device__ float g_valid[T_ROWS];             // indexed by (p<<6)|i
__device__ int   g_idx[T_ROWS];               // indexed by (slot<<6)|i
__device__ int   g_pred[BITS];
__device__ int   g_u;
__device__ int   g_plist[BITS];
__device__ int   g_pred_slot[BITS];

__device__ __forceinline__ float tf32_hi(float a) {
    return __uint_as_float(__float_as_uint(a) & 0xFFFFE000u);
}

// ---------------------------------------------------------------------------
// D1: decoder layer1 as split-K GEMM; A built on the fly from Ws0 rows.
// grid (12, KSD), 256 thr, BK=16.
// ---------------------------------------------------------------------------
__global__ __launch_bounds__(256)
void dec_l1_kernel(const float* __restrict__ Ws0, const float* __restrict__ bs0,
                   const float* __restrict__ Ws1) {
    const int BK = 16;
    int n0 = blockIdx.x * 64;
    int k0 = blockIdx.y * KSLICED;

    __shared__ __align__(16) float As[BK][64];
    __shared__ __align__(16) float Bs[BK][64];

    int tid = threadIdx.x;
    int ty = tid >> 4, tx = tid & 15;
    int aRow = tid >> 2;          // s value 0..63
    int aK   = (tid & 3) * 4;
    int bRow = tid >> 4;
    int bCol = (tid & 15) * 4;

    float acc[4][4] = {};

    #pragma unroll 1
    for (int kt = 0; kt < KSLICED; kt += BK) {
        int gk = k0 + kt + aK;
        float4 v = *(const float4*)(bs0 + gk);
        #pragma unroll
        for (int b = 0; b < 6; b++) {
            if ((aRow >> b) & 1) {
                float4 w = *(const float4*)(Ws0 + (size_t)b * HID + gk);
                v.x += w.x; v.y += w.y; v.z += w.z; v.w += w.w;
            }
        }
        As[aK + 0][aRow] = fmaxf(v.x, 0.f);
        As[aK + 1][aRow] = fmaxf(v.y, 0.f);
        As[aK + 2][aRow] = fmaxf(v.z, 0.f);
        As[aK + 3][aRow] = fmaxf(v.w, 0.f);
        float4 bv = *(const float4*)(Ws1 + (size_t)(k0 + kt + bRow) * HID + n0 + bCol);
        *(float4*)&Bs[bRow][bCol] = bv;
        __syncthreads();

        #pragma unroll
        for (int k = 0; k < BK; k++) {
            float aF[4], bF[4];
            *(float4*)aF = *(const float4*)&As[k][ty * 4];
            *(float4*)bF = *(const float4*)&Bs[k][tx * 4];
            #pragma unroll
            for (int m = 0; m < 4; m++)
                #pragma unroll
                for (int n = 0; n < 4; n++)
                    acc[m][n] = fmaf(aF[m], bF[n], acc[m][n]);
        }
        __syncthreads();
    }

    #pragma unroll
    for (int m = 0; m < 4; m++) {
        float4 o;
        o.x = acc[m][0]; o.y = acc[m][1]; o.z = acc[m][2]; o.w = acc[m][3];
        *(float4*)&g_d1[blockIdx.y][ty * 4 + m][n0 + tx * 4] = o;
    }
}

// ---------------------------------------------------------------------------
// D2: decoder layer2 + argmax. One block per s.
// ---------------------------------------------------------------------------
__global__ __launch_bounds__(256)
void dec_l2_kernel(const float* __restrict__ bs1,
                   const float* __restrict__ Ws2, const float* __restrict__ bs2) {
    int s = blockIdx.x;
    int tid = threadIdx.x;
    __shared__ __align__(16) float h1[HID];
    __shared__ __align__(16) float part[4][BITS];
    __shared__ __align__(16) float lg[BITS];

    #pragma unroll
    for (int r = 0; r < 3; r++) {
        int j = tid + r * 256;
        float v = bs1[j];
        #pragma unroll
        for (int sl = 0; sl < KSD; sl++) v += g_d1[sl][s][j];
        h1[j] = fmaxf(v, 0.f);
    }
    __syncthreads();

    int col = tid & 63;
    int chunk = tid >> 6;                 // 0..3
    float p = 0.f;
    int kb = chunk * (HID / 4);
    for (int k = 0; k < HID / 4; k++)
        p = fmaf(h1[kb + k], Ws2[(size_t)(kb + k) * BITS + col], p);
    part[chunk][col] = p;
    __syncthreads();

    if (tid < BITS)
        lg[tid] = part[0][tid] + part[1][tid] + part[2][tid] + part[3][tid] + bs2[tid];
    __syncthreads();

    if (tid == 0) {
        float best = lg[0]; int bi = 0;
        for (int c = 1; c < BITS; c++)
            if (lg[c] > best) { best = lg[c]; bi = c; }
        g_pred[s] = bi;
    }
}

// ---------------------------------------------------------------------------
// V: validity for ALL 4096 (p,i) rows, warp-per-row; block 0 compacts preds
// (runs after dec_l2 in single-stream order; zero extra nodes).
// ---------------------------------------------------------------------------
__global__ __launch_bounds__(256)
void valid_kernel(const float* __restrict__ Wv0, const float* __restrict__ bv0,
                  const float* __restrict__ Wv1, const float* __restrict__ bv1) {
    int warp = threadIdx.x >> 5;
    int lane = threadIdx.x & 31;
    int t = blockIdx.x * 8 + warp;
    int p = t >> 6;
    int i = t & 63;

    const float* vp = Wv0 + (size_t)(BITS + p) * (HID / 2);
    const float* vi = Wv0 + (size_t)i * (HID / 2);
    float part = 0.f;
    #pragma unroll
    for (int r = 0; r < 12; r++) {
        int j = lane + r * 32;
        part += fmaxf(vp[j] + vi[j] + bv0[j], 0.f) * Wv1[j];
    }
    #pragma unroll
    for (int off = 16; off > 0; off >>= 1)
        part += __shfl_down_sync(0xffffffff, part, off);
    if (lane == 0) {
        float v = part + bv1[0];
        g_valid[t] = 1.f / (1.f + expf(-v));
    }

    if (blockIdx.x == 0) {
        __shared__ int used[BITS];
        __shared__ int slot[BITS];
        int tid = threadIdx.x;
        if (tid < BITS) used[tid] = 0;
        __syncthreads();
        int pr = (tid < BITS) ? g_pred[tid] : 0;
        if (tid < BITS) used[pr] = 1;
        __syncthreads();
        if (tid == 0) {
            int u = 0;
            for (int q = 0; q < BITS; q++)
                if (used[q]) { g_plist[u] = q; slot[q] = u; u++; }
            g_u = u;
        }
        __syncthreads();
        if (tid < BITS) g_pred_slot[tid] = slot[pr];
    }
}

// ---------------------------------------------------------------------------
// G1: gemm1 on tensor cores. BM=64, BN=64, BK=16, KSLICE=128, 256 threads.
// TF32x4: a = a_hi + a_lo (exact split), all 4 cross products accumulated in
// fp32 by the MMA -> fp32-level precision. 8 warps in a 4(M)x2(N) grid; each
// warp owns a 16x32 C tile (2 m16n16k8 accumulators). grid (12, 64, 6).
// ---------------------------------------------------------------------------
__global__ __launch_bounds__(256)
void gemm1_kernel(const float* __restrict__ Wi0, const float* __restrict__ bi0,
                  const float* __restrict__ Wi1) {
    const int BK = 16, BM = 64, BN = 64;
    int sl = blockIdx.y;
    if (sl >= g_u) return;
    int p = g_plist[sl];
    int m0 = sl * BM;
    int n0 = blockIdx.x * BN;
    int k0 = blockIdx.z * KSLICE1;

    __shared__ __align__(16) float Ahi[BK][BM];
    __shared__ __align__(16) float Alo[BK][BM];
    __shared__ __align__(16) float Bhi[BK][BN];
    __shared__ __align__(16) float Blo[BK][BN];
    __shared__ __align__(16) float wpb[KSLICE1];

    int tid = threadIdx.x;
    if (tid < KSLICE1)
        wpb[tid] = Wi0[(size_t)(BITS + p) * HID + k0 + tid] + bi0[k0 + tid];

    int warpId = tid >> 5;
    int wm = warpId & 3;                   // 0..3 -> rows wm*16
    int wn = warpId >> 2;                  // 0..1 -> cols wn*32

    // A-build mapping: m = tid&63, covers kk4..kk4+3 (float4 from Wi0 row m)
    int am  = tid & 63;
    int ak4 = (tid >> 6) * 4;
    const float* WiRow = Wi0 + (size_t)am * HID + k0;
    // B mapping: n = tid&63, covers kk = (tid>>6) + 4*j (coalesced rows)
    int bn  = tid & 63;
    int bk0 = tid >> 6;

    wmma::fragment<wmma::accumulator, 16, 16, 8, float> acc0, acc1;
    wmma::fill_fragment(acc0, 0.0f);
    wmma::fill_fragment(acc1, 0.0f);

    __syncthreads();                       // wpb ready

    #pragma unroll 1
    for (int kt = 0; kt < KSLICE1; kt += BK) {
        // build A tile (fused relu(Wi0[i] + Wp + bi0)), split hi/lo
        {
            float4 w = *(const float4*)(WiRow + kt + ak4);
            float av[4] = {w.x, w.y, w.z, w.w};
            #pragma unroll
            for (int j = 0; j < 4; j++) {
                float a = fmaxf(av[j] + wpb[kt + ak4 + j], 0.f);
                float hi = tf32_hi(a);
                Ahi[ak4 + j][am] = hi;
                Alo[ak4 + j][am] = a - hi;
            }
        }
        // build B tile, split hi/lo (coalesced)
        #pragma unroll
        for (int j = 0; j < 4; j++) {
            int kk = bk0 + j * 4;
            float b = Wi1[(size_t)(k0 + kt + kk) * HID + n0 + bn];
            float hi = tf32_hi(b);
            Bhi[kk][bn] = hi;
            Blo[kk][bn] = b - hi;
        }
        __syncthreads();

        #pragma unroll
        for (int s = 0; s < 2; s++) {
            wmma::fragment<wmma::matrix_a, 16, 16, 8, wmma::precision::tf32, wmma::col_major> aH, aL;
            wmma::fragment<wmma::matrix_b, 16, 16, 8, wmma::precision::tf32, wmma::row_major> bH0, bL0, bH1, bL1;

            wmma::load_matrix_sync(aH, &Ahi[s * 8][wm * 16], BM);
            wmma::load_matrix_sync(aL, &Alo[s * 8][wm * 16], BM);
            wmma::load_matrix_sync(bH0, &Bhi[s * 8][wn * 32], BN);
            wmma::load_matrix_sync(bL0, &Blo[s * 8][wn * 32], BN);
            wmma::load_matrix_sync(bH1, &Bhi[s * 8][wn * 32 + 16], BN);
            wmma::load_matrix_sync(bL1, &Blo[s * 8][wn * 32 + 16], BN);

            #pragma unroll
            for (int e = 0; e < aH.num_elements; e++) {
                aH.x[e] = wmma::__float_to_tf32(aH.x[e]);
                aL.x[e] = wmma::__float_to_tf32(aL.x[e]);
            }
            #pragma unroll
            for (int e = 0; e < bH0.num_elements; e++) {
                bH0.x[e] = wmma::__float_to_tf32(bH0.x[e]);
                bL0.x[e] = wmma::__float_to_tf32(bL0.x[e]);
                bH1.x[e] = wmma::__float_to_tf32(bH1.x[e]);
                bL1.x[e] = wmma::__float_to_tf32(bL1.x[e]);
            }

            wmma::mma_sync(acc0, aH, bH0, acc0);
            wmma::mma_sync(acc0, aH, bL0, acc0);
            wmma::mma_sync(acc0, aL, bH0, acc0);
            wmma::mma_sync(acc0, aL, bL0, acc0);

            wmma::mma_sync(acc1, aH, bH1, acc1);
            wmma::mma_sync(acc1, aH, bL1, acc1);
            wmma::mma_sync(acc1, aL, bH1, acc1);
            wmma::mma_sync(acc1, aL, bL1, acc1);
        }
        __syncthreads();
    }

    float* dst = &g_p1[blockIdx.z][m0 + wm * 16][n0 + wn * 32];
    wmma::store_matrix_sync(dst, acc0, HID, wmma::mem_row_major);
    wmma::store_matrix_sync(dst + 16, acc1, HID, wmma::mem_row_major);
}

// ---------------------------------------------------------------------------
// G2: gemm2 split-K; combine (sum KS1 partials + bias + relu) fused into
// A-load. BM=32, BN=64, BK=16, grid (128, KS2).
// ---------------------------------------------------------------------------
__global__ __launch_bounds__(256)
void gemm2_kernel(const float* __restrict__ bi1, const float* __restrict__ Wi2) {
    const int BM = 32, BK = 16;
    int m0 = blockIdx.x * BM;
    if (m0 >= g_u * BITS) return;
    int k0 = blockIdx.y * KSLICE2;

    __shared__ __align__(16) float As[BK][BM];
    __shared__ __align__(16) float Bs[BK][BITS];

    int tid = threadIdx.x;
    int ty = tid >> 4, tx = tid & 15;
    int aRow = (tid >> 2) & 31;
    int aK   = (tid & 3) * 4;
    int bRow = tid >> 4;
    int bCol = (tid & 15) * 4;

    float acc[2][4] = {};

    #pragma unroll 1
    for (int kt = 0; kt < KSLICE2; kt += BK) {
        if (tid < 128) {
            int gk = k0 + kt + aK;
            int m = m0 + aRow;
            float4 s = *(const float4*)&g_p1[0][m][gk];
            #pragma unroll
            for (int sl = 1; sl < KS1; sl++) {
                float4 t = *(const float4*)&g_p1[sl][m][gk];
                s.x += t.x; s.y += t.y; s.z += t.z; s.w += t.w;
            }
            float4 b = *(const float4*)(bi1 + gk);
            As[aK + 0][aRow] = fmaxf(s.x + b.x, 0.f);
            As[aK + 1][aRow] = fmaxf(s.y + b.y, 0.f);
            As[aK + 2][aRow] = fmaxf(s.z + b.z, 0.f);
            As[aK + 3][aRow] = fmaxf(s.w + b.w, 0.f);
        }
        float4 bv = *(const float4*)(Wi2 + (size_t)(k0 + kt + bRow) * BITS + bCol);
        *(float4*)&Bs[bRow][bCol] = bv;
        __syncthreads();

        #pragma unroll
        for (int k = 0; k < BK; k++) {
            float aF[2], bF[4];
            aF[0] = As[k][ty * 2 + 0];
            aF[1] = As[k][ty * 2 + 1];
            *(float4*)bF = *(const float4*)&Bs[k][tx * 4];
            #pragma unroll
            for (int m = 0; m < 2; m++)
                #pragma unroll
                for (int n = 0; n < 4; n++)
                    acc[m][n] = fmaf(aF[m], bF[n], acc[m][n]);
        }
        __syncthreads();
    }

    #pragma unroll
    for (int m = 0; m < 2; m++) {
        float4 o;
        o.x = acc[m][0]; o.y = acc[m][1]; o.z = acc[m][2]; o.w = acc[m][3];
        *(float4*)&g_part[blockIdx.y][m0 + ty * 2 + m][tx * 4] = o;
    }
}

// ---------------------------------------------------------------------------
// argmax over summed gemm2 partials. One warp per table row.
// ---------------------------------------------------------------------------
__global__ __launch_bounds__(256)
void argmax_kernel(const float* __restrict__ bi2) {
    int warp = threadIdx.x >> 5;
    int lane = threadIdx.x & 31;
    int row = blockIdx.x * 8 + warp;
    if (row >= g_u * BITS) return;

    float v0 = bi2[lane];
    float v1 = bi2[lane + 32];
    #pragma unroll
    for (int s = 0; s < KS2; s++) {
        v0 += g_part[s][row][lane];
        v1 += g_part[s][row][lane + 32];
    }
    float best = v0; int bi = lane;
    if (v1 > best) { best = v1; bi = lane + 32; }

    #pragma unroll
    for (int off = 16; off > 0; off >>= 1) {
        float ob = __shfl_down_sync(0xffffffff, best, off);
        int   oi = __shfl_down_sync(0xffffffff, bi, off);
        if (ob > best || (ob == best && oi < bi)) { best = ob; bi = oi; }
    }
    if (lane == 0) g_idx[row] = bi;
}

// ---------------------------------------------------------------------------
// out: warp per batch row; gather via shfl. valid indexed by p, idx by slot.
// ---------------------------------------------------------------------------
__global__ __launch_bounds__(256)
void out_kernel(const float* __restrict__ a_bits, const int* __restrict__ shift,
                float* __restrict__ out, int B) {
    int warp = threadIdx.x >> 5;
    int lane = threadIdx.x & 31;
    int b = blockIdx.x * 8 + warp;
    if (b >= B) return;

    const float* arow = a_bits + ((size_t)b << 6);
    float a0 = arow[lane];
    float a1 = arow[lane + 32];
    int sv = shift[b];
    int p  = g_pred[sv];
    int sl = g_pred_slot[sv];
    int tp = p << 6;
    int tb = sl << 6;

    int   i0 = g_idx[tb + lane];
    int   i1 = g_idx[tb + lane + 32];
    float v0 = g_valid[tp + lane];
    float v1 = g_valid[tp + lane + 32];

    float c00 = __shfl_sync(0xffffffff, a0, i0 & 31);
    float c01 = __shfl_sync(0xffffffff, a1, i0 & 31);
    float c10 = __shfl_sync(0xffffffff, a0, i1 & 31);
    float c11 = __shfl_sync(0xffffffff, a1, i1 & 31);

    float g0 = (i0 < 32) ? c00 : c01;
    float g1 = (i1 < 32) ? c10 : c11;

    out[((size_t)b << 6) + lane]      = g0 * v0;
    out[((size_t)b << 6) + lane + 32] = g1 * v1;
}

// ---------------------------------------------------------------------------
extern "C" void kernel_launch(void* const* d_in, const int* in_sizes, int n_in,
                              void* d_out, int out_size) {
    const float* a_bits = (const float*)d_in[0];
    const int*   shift  = (const int*)d_in[1];
    const float* Ws0 = (const float*)d_in[2];
    const float* bs0 = (const float*)d_in[3];
    const float* Ws1 = (const float*)d_in[4];
    const float* bs1 = (const float*)d_in[5];
    const float* Ws2 = (const float*)d_in[6];
    const float* bs2 = (const float*)d_in[7];
    const float* Wi0 = (const float*)d_in[8];
    const float* bi0 = (const float*)d_in[9];
    const float* Wi1 = (const float*)d_in[10];
    const float* bi1 = (const float*)d_in[11];
    const float* Wi2 = (const float*)d_in[12];
    const float* bi2 = (const float*)d_in[13];
    const float* Wv0 = (const float*)d_in[14];
    const float* bv0 = (const float*)d_in[15];
    const float* Wv1 = (const float*)d_in[16];
    const float* bv1 = (const float*)d_in[17];
    float* out = (float*)d_out;

    int B = in_sizes[1];               // 32768

    dim3 gd(HID / 64, KSD);                        // (12, 6)
    dec_l1_kernel<<<gd, 256>>>(Ws0, bs0, Ws1);
    dec_l2_kernel<<<BITS, 256>>>(bs1, Ws2, bs2);
    valid_kernel<<<T_ROWS / 8, 256>>>(Wv0, bv0, Wv1, bv1);

    dim3 g1(HID / 64, BITS, KS1);                  // (12, 64, 6)
    gemm1_kernel<<<g1, 256>>>(Wi0, bi0, Wi1);

    dim3 g2(T_ROWS / 32, KS2);                     // (128, 8)
    gemm2_kernel<<<g2, 256>>>(bi1, Wi2);
    argmax_kernel<<<T_ROWS / 8, 256>>>(bi2);

    out_kernel<<<(B + 7) / 8, 256>>>(a_bits, shift, out, B);
}